// round 15
// baseline (speedup 1.0000x reference)
#include <cuda_runtime.h>
#include <cuda_bf16.h>
#include <cuda_fp16.h>
#include <math.h>

#define NB 4
#define NS 2048
#define ND 512
#define NH 8
#define NDK 64
#define LOG2E 1.4426950408889634f
#define SCL2 (0.125f * LOG2E)
#define MINIT (-1e30f)
#define KT 128
#define NTILE (NS / KT)

typedef unsigned int u32;
typedef __nv_bfloat16 bf16;

// ---------------- scratch ----------------
__device__ bf16 g_Ah[(size_t)3 * NB * NS * ND];
__device__ bf16 g_Al[(size_t)3 * NB * NS * ND];
__device__ bf16 g_Wh[(size_t)4 * ND * ND];
__device__ bf16 g_Wl[(size_t)4 * ND * ND];
__device__ bf16 g_Qh[(size_t)NB * NH * NS * NDK];
__device__ bf16 g_Ql[(size_t)NB * NH * NS * NDK];
__device__ bf16 g_Kh[(size_t)NB * NH * NS * NDK];
__device__ bf16 g_Kl[(size_t)NB * NH * NS * NDK];
__device__ bf16 g_Vh[(size_t)NB * NH * NS * NDK];
__device__ bf16 g_Vl[(size_t)NB * NH * NS * NDK];
__device__ bf16 g_Ch[(size_t)NB * NS * ND];
__device__ bf16 g_Cl[(size_t)NB * NS * ND];
__device__ float g_M[(size_t)NB * NH * NS];
__device__ float g_Z[(size_t)NB * NH * NS];    // 1/Z
__device__ float g_Mt[(size_t)NB * NH * NTILE * NS];
__device__ float g_madd[(size_t)NB * NS];
__device__ int   g_maskkind;
__device__ u32 g_S[(size_t)NB * NS * NH * NS / 2];  // fp16x2 tile-local probs

// ---------------- helpers ----------------
__device__ __forceinline__ float bfround(float x) {
    return __bfloat162float(__float2bfloat16(x));
}
__device__ __forceinline__ u32 packbf(float lo_el, float hi_el) {
    u32 r;
    asm("cvt.rn.bf16x2.f32 %0, %1, %2;" : "=r"(r) : "f"(hi_el), "f"(lo_el));
    return r;
}
__device__ __forceinline__ u32 packhf(float lo_el, float hi_el) {
    u32 r;
    asm("cvt.rn.f16x2.f32 %0, %1, %2;" : "=r"(r) : "f"(hi_el), "f"(lo_el));
    return r;
}
__device__ __forceinline__ float2 h2f2(u32 v) {
    __half2 h = *(__half2*)&v;
    return __half22float2(h);
}
__device__ __forceinline__ float ex2f(float x) {
    float y;
    asm("ex2.approx.f32 %0, %1;" : "=f"(y) : "f"(x));
    return y;
}
__device__ __forceinline__ void mma_bf16(float d[4], const u32 a[4], u32 b0, u32 b1) {
    asm volatile(
        "mma.sync.aligned.m16n8k16.row.col.f32.bf16.bf16.f32 "
        "{%0,%1,%2,%3}, {%4,%5,%6,%7}, {%8,%9}, {%0,%1,%2,%3};"
        : "+f"(d[0]), "+f"(d[1]), "+f"(d[2]), "+f"(d[3])
        : "r"(a[0]), "r"(a[1]), "r"(a[2]), "r"(a[3]), "r"(b0), "r"(b1));
}
__device__ __forceinline__ u32 smem_u32p(const void* p) {
    u32 a;
    asm("{ .reg .u64 t; cvta.to.shared.u64 t, %1; cvt.u32.u64 %0, t; }" : "=r"(a) : "l"(p));
    return a;
}
__device__ __forceinline__ void ldsm_x4(u32* r, u32 a) {
    asm volatile("ldmatrix.sync.aligned.m8n8.x4.shared.b16 {%0,%1,%2,%3}, [%4];"
                 : "=r"(r[0]), "=r"(r[1]), "=r"(r[2]), "=r"(r[3]) : "r"(a));
}
__device__ __forceinline__ void ldsm_x4_t(u32* r, u32 a) {
    asm volatile("ldmatrix.sync.aligned.m8n8.x4.trans.shared.b16 {%0,%1,%2,%3}, [%4];"
                 : "=r"(r[0]), "=r"(r[1]), "=r"(r[2]), "=r"(r[3]) : "r"(a));
}

// ---------------- mask sniff / convert (validated R2) ----------------
__global__ void mask_detect(const unsigned char* __restrict__ mraw) {
    __shared__ int s_not01, s_oneOther, s_3fOdd;
    if (threadIdx.x == 0) { s_not01 = 0; s_oneOther = 0; s_3fOdd = 0; }
    __syncthreads();
    int l_not01 = 0, l_oneOther = 0, l_3fOdd = 0;
    for (int i = threadIdx.x; i < NB * NS; i += blockDim.x) {
        const unsigned char v = mraw[i];
        if (v > 1) l_not01++;
        if (v == 1 && (i & 3) != 0) l_oneOther++;
        if (v == 0x3f && (i & 3) == 1) l_3fOdd++;
    }
    atomicAdd(&s_not01, l_not01);
    atomicAdd(&s_oneOther, l_oneOther);
    atomicAdd(&s_3fOdd, l_3fOdd);
    __syncthreads();
    if (threadIdx.x == 0) {
        int kind;
        if (s_not01 > 0)          kind = (s_3fOdd > 0) ? 3 : 2;
        else if (s_oneOther == 0) kind = 1;
        else                      kind = 0;
        g_maskkind = kind;
    }
}

__global__ void mask_convert(const void* __restrict__ mraw) {
    const int i = blockIdx.x * blockDim.x + threadIdx.x;
    if (i >= NB * NS) return;
    const int kind = g_maskkind;
    bool on;
    if (kind == 0)      on = ((const unsigned char*)mraw)[i] != 0;
    else if (kind == 1) on = ((const int*)mraw)[i] != 0;
    else if (kind == 2) on = ((const float*)mraw)[i] != 0.f;
    else                on = ((const unsigned short*)mraw)[i] != 0;
    g_madd[i] = on ? 0.f : -INFINITY;
}

// ---------------- splits ----------------
__global__ void split_in(const float* __restrict__ s0, const float* __restrict__ s1,
                         const float* __restrict__ s2) {
    const int z = blockIdx.z;
    const float* s = (z == 0) ? s0 : (z == 1) ? s1 : s2;
    bf16* h = g_Ah + (size_t)z * NB * NS * ND;
    bf16* l = g_Al + (size_t)z * NB * NS * ND;
    const int i = (blockIdx.x * blockDim.x + threadIdx.x) * 4;
    float4 v = *(const float4*)&s[i];
    uint2 hh, ll;
    hh.x = packbf(v.x, v.y);
    hh.y = packbf(v.z, v.w);
    ll.x = packbf(v.x - bfround(v.x), v.y - bfround(v.y));
    ll.y = packbf(v.z - bfround(v.z), v.w - bfround(v.w));
    *(uint2*)&h[i] = hh;
    *(uint2*)&l[i] = ll;
}

__global__ void split_w(const float* __restrict__ s0, const float* __restrict__ s1,
                        const float* __restrict__ s2, const float* __restrict__ s3) {
    const int z = blockIdx.z;
    const float* s = (z == 0) ? s0 : (z == 1) ? s1 : (z == 2) ? s2 : s3;
    bf16* h = g_Wh + (size_t)z * ND * ND;
    bf16* l = g_Wl + (size_t)z * ND * ND;
    const int i = (blockIdx.x * blockDim.x + threadIdx.x) * 4;
    float4 v = *(const float4*)&s[i];
    uint2 hh, ll;
    hh.x = packbf(v.x, v.y);
    hh.y = packbf(v.z, v.w);
    ll.x = packbf(v.x - bfround(v.x), v.y - bfround(v.y));
    ll.y = packbf(v.z - bfround(v.z), v.w - bfround(v.w));
    *(uint2*)&h[i] = hh;
    *(uint2*)&l[i] = ll;
}

// ---------------------------------------------------------------------------
// QKV projections (R12 plain-LDS version — fastest measured). grid (4, 64, 3).
// ---------------------------------------------------------------------------
__global__ __launch_bounds__(256) void proj_qkv(const float* __restrict__ b0p,
                                                const float* __restrict__ b1p,
                                                const float* __restrict__ b2p) {
    __shared__ __align__(16) bf16 Xsh[128 * 40], Xsl[128 * 40];
    __shared__ __align__(16) bf16 Wsh[128 * 40], Wsl[128 * 40];

    const int z = blockIdx.z;
    const bf16* Xh = g_Ah + (size_t)z * NB * NS * ND;
    const bf16* Xl = g_Al + (size_t)z * NB * NS * ND;
    const bf16* Wh = g_Wh + (size_t)z * ND * ND;
    const bf16* Wl = g_Wl + (size_t)z * ND * ND;
    const float* bias = (z == 0) ? b0p : (z == 1) ? b1p : b2p;
    bf16* Yh = (z == 0) ? g_Qh : (z == 1) ? g_Kh : g_Vh;
    bf16* Yl = (z == 0) ? g_Ql : (z == 1) ? g_Kl : g_Vl;

    const int tid = threadIdx.x;
    const int w = tid >> 5, lane = tid & 31, g = lane >> 2, t = lane & 3;
    const int m0 = blockIdx.y * 128, n0 = blockIdx.x * 128;
    const int mw = (w >> 1) * 32, nw = (w & 1) * 64;

    float D[2][8][4];
#pragma unroll
    for (int mi = 0; mi < 2; mi++)
#pragma unroll
        for (int nt = 0; nt < 8; nt++)
#pragma unroll
            for (int j = 0; j < 4; j++) D[mi][nt][j] = 0.f;

    const int lrow = tid >> 2, lcol = (tid & 3) * 8;

    for (int k0 = 0; k0 < ND; k0 += 32) {
#pragma unroll
        for (int p = 0; p < 2; p++) {
            const int row = lrow + 64 * p;
            *(uint4*)&Xsh[row * 40 + lcol] = *(const uint4*)&Xh[(size_t)(m0 + row) * ND + k0 + lcol];
            *(uint4*)&Xsl[row * 40 + lcol] = *(const uint4*)&Xl[(size_t)(m0 + row) * ND + k0 + lcol];
            *(uint4*)&Wsh[row * 40 + lcol] = *(const uint4*)&Wh[(size_t)(n0 + row) * ND + k0 + lcol];
            *(uint4*)&Wsl[row * 40 + lcol] = *(const uint4*)&Wl[(size_t)(n0 + row) * ND + k0 + lcol];
        }
        __syncthreads();

        const u32* XH = (const u32*)Xsh;
        const u32* XL = (const u32*)Xsl;
        const u32* WH = (const u32*)Wsh;
        const u32* WL = (const u32*)Wsl;
#pragma unroll
        for (int c = 0; c < 2; c++) {
            u32 aH[2][4], aL[2][4];
#pragma unroll
            for (int mi = 0; mi < 2; mi++) {
                const int r0 = (mw + 16 * mi + g) * 20 + 8 * c + t;
                const int r1 = (mw + 16 * mi + g + 8) * 20 + 8 * c + t;
                aH[mi][0] = XH[r0]; aH[mi][1] = XH[r1];
                aH[mi][2] = XH[r0 + 4]; aH[mi][3] = XH[r1 + 4];
                aL[mi][0] = XL[r0]; aL[mi][1] = XL[r1];
                aL[mi][2] = XL[r0 + 4]; aL[mi][3] = XL[r1 + 4];
            }
#pragma unroll
            for (int nt = 0; nt < 8; nt++) {
                const int nb = (nw + 8 * nt + g) * 20 + 8 * c + t;
                const u32 bh0 = WH[nb], bh1 = WH[nb + 4];
                const u32 bl0 = WL[nb], bl1 = WL[nb + 4];
#pragma unroll
                for (int mi = 0; mi < 2; mi++) {
                    mma_bf16(D[mi][nt], aH[mi], bh0, bh1);
                    mma_bf16(D[mi][nt], aH[mi], bl0, bl1);
                    mma_bf16(D[mi][nt], aL[mi], bh0, bh1);
                }
            }
        }
        __syncthreads();
    }

#pragma unroll
    for (int mi = 0; mi < 2; mi++) {
#pragma unroll
        for (int nt = 0; nt < 8; nt++) {
            const int n = n0 + nw + 8 * nt + 2 * t;
            const float bb0 = bias[n], bb1 = bias[n + 1];
            const int h = n >> 6, dk = n & 63;
#pragma unroll
            for (int rr = 0; rr < 2; rr++) {
                const int m = m0 + mw + 16 * mi + g + 8 * rr;
                const float v0 = D[mi][nt][2 * rr + 0] + bb0;
                const float v1 = D[mi][nt][2 * rr + 1] + bb1;
                const int b = m >> 11, s = m & (NS - 1);
                const size_t off = (((size_t)(b * NH + h)) * NS + s) * NDK + dk;
                *(u32*)&Yh[off] = packbf(v0, v1);
                *(u32*)&Yl[off] = packbf(v0 - bfround(v0), v1 - bfround(v1));
            }
        }
    }
}

// ---------------------------------------------------------------------------
// Output projection (R12 plain-LDS version)
// ---------------------------------------------------------------------------
__global__ __launch_bounds__(256) void proj_out(const float* __restrict__ bias,
                                                float* __restrict__ out) {
    __shared__ __align__(16) bf16 Xsh[128 * 40], Xsl[128 * 40];
    __shared__ __align__(16) bf16 Wsh[128 * 40], Wsl[128 * 40];

    const bf16* Xh = g_Ch;
    const bf16* Xl = g_Cl;
    const bf16* Wh = g_Wh + (size_t)3 * ND * ND;
    const bf16* Wl = g_Wl + (size_t)3 * ND * ND;

    const int tid = threadIdx.x;
    const int w = tid >> 5, lane = tid & 31, g = lane >> 2, t = lane & 3;
    const int m0 = blockIdx.y * 128, n0 = blockIdx.x * 128;
    const int mw = (w >> 1) * 32, nw = (w & 1) * 64;

    float D[2][8][4];
#pragma unroll
    for (int mi = 0; mi < 2; mi++)
#pragma unroll
        for (int nt = 0; nt < 8; nt++)
#pragma unroll
            for (int j = 0; j < 4; j++) D[mi][nt][j] = 0.f;

    const int lrow = tid >> 2, lcol = (tid & 3) * 8;

    for (int k0 = 0; k0 < ND; k0 += 32) {
#pragma unroll
        for (int p = 0; p < 2; p++) {
            const int row = lrow + 64 * p;
            *(uint4*)&Xsh[row * 40 + lcol] = *(const uint4*)&Xh[(size_t)(m0 + row) * ND + k0 + lcol];
            *(uint4*)&Xsl[row * 40 + lcol] = *(const uint4*)&Xl[(size_t)(m0 + row) * ND + k0 + lcol];
            *(uint4*)&Wsh[row * 40 + lcol] = *(const uint4*)&Wh[(size_t)(n0 + row) * ND + k0 + lcol];
            *(uint4*)&Wsl[row * 40 + lcol] = *(const uint4*)&Wl[(size_t)(n0 + row) * ND + k0 + lcol];
        }
        __syncthreads();

        const u32* XH = (const u32*)Xsh;
        const u32* XL = (const u32*)Xsl;
        const u32* WH = (const u32*)Wsh;
        const u32* WL = (const u32*)Wsl;
#pragma unroll
        for (int c = 0; c < 2; c++) {
            u32 aH[2][4], aL[2][4];
#pragma unroll
            for (int mi = 0; mi < 2; mi++) {
                const int r0 = (mw + 16 * mi + g) * 20 + 8 * c + t;
                const int r1 = (mw + 16 * mi + g + 8) * 20 + 8 * c + t;
                aH[mi][0] = XH[r0]; aH[mi][1] = XH[r1];
                aH[mi][2] = XH[r0 + 4]; aH[mi][3] = XH[r1 + 4];
                aL[mi][0] = XL[r0]; aL[mi][1] = XL[r1];
                aL[mi][2] = XL[r0 + 4]; aL[mi][3] = XL[r1 + 4];
            }
#pragma unroll
            for (int nt = 0; nt < 8; nt++) {
                const int nb = (nw + 8 * nt + g) * 20 + 8 * c + t;
                const u32 bh0 = WH[nb], bh1 = WH[nb + 4];
                const u32 bl0 = WL[nb], bl1 = WL[nb + 4];
#pragma unroll
                for (int mi = 0; mi < 2; mi++) {
                    mma_bf16(D[mi][nt], aH[mi], bh0, bh1);
                    mma_bf16(D[mi][nt], aH[mi], bl0, bl1);
                    mma_bf16(D[mi][nt], aL[mi], bh0, bh1);
                }
            }
        }
        __syncthreads();
    }

#pragma unroll
    for (int mi = 0; mi < 2; mi++) {
#pragma unroll
        for (int nt = 0; nt < 8; nt++) {
            const int n = n0 + nw + 8 * nt + 2 * t;
            const float bb0 = bias[n], bb1 = bias[n + 1];
#pragma unroll
            for (int rr = 0; rr < 2; rr++) {
                const int m = m0 + mw + 16 * mi + g + 8 * rr;
                float2 v = make_float2(D[mi][nt][2 * rr + 0] + bb0,
                                       D[mi][nt][2 * rr + 1] + bb1);
                *(float2*)&out[(size_t)m * ND + n] = v;
            }
        }
    }
}

// ---------------------------------------------------------------------------
// attn.mean (R12 structure; tile index now k>>7 to match KT=128)
// ---------------------------------------------------------------------------
__global__ __launch_bounds__(256) void mean_ew(float* __restrict__ out) {
    const int b = blockIdx.z;
    const int q = blockIdx.y;
    const int k = threadIdx.x * 8;
    const int tile = k >> 7;

    const u32* Pbase = g_S + (((size_t)(b * NS + q) * NH) * NS + k >> 1);
    float acc[8];
#pragma unroll
    for (int j = 0; j < 8; j++) acc[j] = 0.f;

#pragma unroll
    for (int h = 0; h < NH; h++) {
        const size_t bh = (size_t)(b * NH + h);
        const float m = g_M[bh * NS + q];
        const float zi = g_Z[bh * NS + q];
        const float mt = g_Mt[(bh * NTILE + tile) * NS + q];
        const float corr = ex2f(mt - m) * zi;
        uint4 pv = *(const uint4*)&Pbase[(size_t)h * (NS >> 1)];
        float2 p0 = h2f2(pv.x), p1 = h2f2(pv.y), p2 = h2f2(pv.z), p3 = h2f2(pv.w);
        acc[0] += p0.x * corr; acc[1] += p0.y * corr;
        acc[2] += p1.x * corr; acc[3] += p1.y * corr;
        acc[4] += p2.x * corr; acc[5] += p2.y * corr;
        acc[6] += p3.x * corr; acc[7] += p3.y * corr;
    }
    float4 oA = make_float4(acc[0] * 0.125f, acc[1] * 0.125f, acc[2] * 0.125f, acc[3] * 0.125f);
    float4 oB = make_float4(acc[4] * 0.125f, acc[5] * 0.125f, acc[6] * 0.125f, acc[7] * 0.125f);
    float* orow = &out[((size_t)(b * NS + q)) * NS + k];
    *(float4*)&orow[0] = oA;
    *(float4*)&orow[4] = oB;
}

// ---------------------------------------------------------------------------
// Flash attention: 128q x 128k tiles (dynamic smem 73.7KB, 1 CTA/SM, 8 warps).
// ldmatrix fragment loads (validated R12 mappings). Halves per-tile overhead.
// ---------------------------------------------------------------------------
#define FLASH_SMEM ((size_t)4 * KT * 72 * sizeof(bf16))

__global__ __launch_bounds__(256, 1) void flash_mma() {
    extern __shared__ __align__(16) bf16 fsm[];
    bf16* Khs = fsm;
    bf16* Kls = Khs + KT * 72;
    bf16* Vhs = Kls + KT * 72;
    bf16* Vls = Vhs + KT * 72;
    __shared__ float madds[KT];

    const int tid = threadIdx.x;
    const int w = tid >> 5, lane = tid & 31, g = lane >> 2, t = lane & 3;
    const int bh = blockIdx.y;
    const int b = bh >> 3, h = bh & 7;
    const int q0 = blockIdx.x * 128;
    const int qw = q0 + 16 * w;

    const bf16* Qhp = g_Qh + (size_t)bh * NS * NDK;
    const bf16* Qlp = g_Ql + (size_t)bh * NS * NDK;
    const bf16* Khp = g_Kh + (size_t)bh * NS * NDK;
    const bf16* Klp = g_Kl + (size_t)bh * NS * NDK;
    const bf16* Vhp = g_Vh + (size_t)bh * NS * NDK;
    const bf16* Vlp = g_Vl + (size_t)bh * NS * NDK;

    u32* Srow0 = g_S + (((size_t)(b * NS + qw + g) * NH + h) * NS >> 1);
    u32* Srow1 = g_S + (((size_t)(b * NS + qw + g + 8) * NH + h) * NS >> 1);

    const u32 kb_h = smem_u32p(Khs), kb_l = smem_u32p(Kls);
    const u32 vb_h = smem_u32p(Vhs), vb_l = smem_u32p(Vls);
    const u32 aoffK = ((lane & 7) * 72 + 8 * (lane >> 3)) * 2;
    const u32 aoffV = (((lane & 7) + 8 * ((lane >> 3) & 1)) * 72 + 8 * (lane >> 4)) * 2;

    u32 qH[4][4], qL[4][4];
#pragma unroll
    for (int c = 0; c < 4; c++) {
        const size_t r0 = (size_t)(qw + g) * NDK + 16 * c + 2 * t;
        const size_t r1 = (size_t)(qw + g + 8) * NDK + 16 * c + 2 * t;
        qH[c][0] = *(const u32*)&Qhp[r0]; qH[c][1] = *(const u32*)&Qhp[r1];
        qH[c][2] = *(const u32*)&Qhp[r0 + 8]; qH[c][3] = *(const u32*)&Qhp[r1 + 8];
        qL[c][0] = *(const u32*)&Qlp[r0]; qL[c][1] = *(const u32*)&Qlp[r1];
        qL[c][2] = *(const u32*)&Qlp[r0 + 8]; qL[c][3] = *(const u32*)&Qlp[r1 + 8];
    }

    float O[8][4];
#pragma unroll
    for (int dt = 0; dt < 8; dt++)
#pragma unroll
        for (int j = 0; j < 4; j++) O[dt][j] = 0.f;
    float m0r = MINIT, m1r = MINIT, z0 = 0.f, z1 = 0.f;

    const int srow = tid >> 3, sseg = tid & 7;

    for (int kt = 0; kt < NS; kt += KT) {
        // ---- stage K and V natural [k][72] ----
#pragma unroll
        for (int p = 0; p < 4; p++) {
            const int row = srow + 32 * p;
            const size_t go = (size_t)(kt + row) * NDK + sseg * 8;
            *(uint4*)&Khs[row * 72 + sseg * 8] = *(const uint4*)&Khp[go];
            *(uint4*)&Kls[row * 72 + sseg * 8] = *(const uint4*)&Klp[go];
            *(uint4*)&Vhs[row * 72 + sseg * 8] = *(const uint4*)&Vhp[go];
            *(uint4*)&Vls[row * 72 + sseg * 8] = *(const uint4*)&Vlp[go];
        }
        if (tid < KT) madds[tid] = g_madd[b * NS + kt + tid];
        __syncthreads();

        // ---- S = Q K^T (16 n-tiles) ----
        float S[16][4];
#pragma unroll
        for (int nt = 0; nt < 16; nt++)
#pragma unroll
            for (int j = 0; j < 4; j++) S[nt][j] = 0.f;
#pragma unroll
        for (int nt = 0; nt < 16; nt++) {
#pragma unroll
            for (int cc = 0; cc < 2; cc++) {
                const u32 off = aoffK + (u32)(8 * nt * 72 + 32 * cc) * 2;
                u32 fH[4], fL[4];
                ldsm_x4(fH, kb_h + off);
                ldsm_x4(fL, kb_l + off);
                mma_bf16(S[nt], qH[2 * cc],     fH[0], fH[1]);
                mma_bf16(S[nt], qH[2 * cc],     fL[0], fL[1]);
                mma_bf16(S[nt], qL[2 * cc],     fH[0], fH[1]);
                mma_bf16(S[nt], qH[2 * cc + 1], fH[2], fH[3]);
                mma_bf16(S[nt], qH[2 * cc + 1], fL[2], fL[3]);
                mma_bf16(S[nt], qL[2 * cc + 1], fH[2], fH[3]);
            }
        }

        // ---- scale + mask, log2-domain online softmax ----
        float rm0 = MINIT, rm1 = MINIT;
#pragma unroll
        for (int nt = 0; nt < 16; nt++) {
            const float ma = madds[8 * nt + 2 * t], mb = madds[8 * nt + 2 * t + 1];
            S[nt][0] = S[nt][0] * SCL2 + ma; S[nt][1] = S[nt][1] * SCL2 + mb;
            S[nt][2] = S[nt][2] * SCL2 + ma; S[nt][3] = S[nt][3] * SCL2 + mb;
            rm0 = fmaxf(rm0, fmaxf(S[nt][0], S[nt][1]));
            rm1 = fmaxf(rm1, fmaxf(S[nt][2], S[nt][3]));
        }
        rm0 = fmaxf(rm0, __shfl_xor_sync(0xffffffffu, rm0, 1));
        rm0 = fmaxf(rm0, __shfl_xor_sync(0xffffffffu, rm0, 2));
        rm1 = fmaxf(rm1, __shfl_xor_sync(0xffffffffu, rm1, 1));
        rm1 = fmaxf(rm1, __shfl_xor_sync(0xffffffffu, rm1, 2));
        const float mn0 = fmaxf(m0r, rm0), mn1 = fmaxf(m1r, rm1);
        const float al0 = ex2f(m0r - mn0);
        const float al1 = ex2f(m1r - mn1);
        if (t == 0) {
            const size_t mtb = ((size_t)bh * NTILE + (kt >> 7)) * NS;
            g_Mt[mtb + qw + g] = mn0;
            g_Mt[mtb + qw + g + 8] = mn1;
        }
        float rs0 = 0.f, rs1 = 0.f;
#pragma unroll
        for (int nt = 0; nt < 16; nt++) {
            const float p0 = ex2f(S[nt][0] - mn0);
            const float p1 = ex2f(S[nt][1] - mn0);
            const float p2 = ex2f(S[nt][2] - mn1);
            const float p3 = ex2f(S[nt][3] - mn1);
            S[nt][0] = p0; S[nt][1] = p1; S[nt][2] = p2; S[nt][3] = p3;
            const int col2 = (kt + 8 * nt + 2 * t) >> 1;
            Srow0[col2] = packhf(p0, p1);
            Srow1[col2] = packhf(p2, p3);
            rs0 += p0 + p1; rs1 += p2 + p3;
        }
        rs0 += __shfl_xor_sync(0xffffffffu, rs0, 1);
        rs0 += __shfl_xor_sync(0xffffffffu, rs0, 2);
        rs1 += __shfl_xor_sync(0xffffffffu, rs1, 1);
        rs1 += __shfl_xor_sync(0xffffffffu, rs1, 2);
        z0 = z0 * al0 + rs0; z1 = z1 * al1 + rs1;
        m0r = mn0; m1r = mn1;
#pragma unroll
        for (int dt = 0; dt < 8; dt++) {
            O[dt][0] *= al0; O[dt][1] *= al0;
            O[dt][2] *= al1; O[dt][3] *= al1;
        }

        // ---- O += P V (8 k16 chunks; pack P per chunk) ----
#pragma unroll
        for (int c = 0; c < 8; c++) {
            u32 pH[4], pL[4];
            {
                const float a0 = S[2 * c][0],     a1 = S[2 * c][1];
                const float a2 = S[2 * c][2],     a3 = S[2 * c][3];
                const float b0 = S[2 * c + 1][0], b1 = S[2 * c + 1][1];
                const float b2 = S[2 * c + 1][2], b3 = S[2 * c + 1][3];
                pH[0] = packbf(a0, a1); pH[1] = packbf(a2, a3);
                pH[2] = packbf(b0, b1); pH[3] = packbf(b2, b3);
                pL[0] = packbf(a0 - bfround(a0), a1 - bfround(a1));
                pL[1] = packbf(a2 - bfround(a2), a3 - bfround(a3));
                pL[2] = packbf(b0 - bfround(b0), b1 - bfround(b1));
                pL[3] = packbf(b2 - bfround(b2), b3 - bfround(b3));
            }
#pragma unroll
            for (int dd = 0; dd < 4; dd++) {
                const u32 off = aoffV + (u32)(16 * c * 72 + 16 * dd) * 2;
                u32 vH[4], vL[4];
                ldsm_x4_t(vH, vb_h + off);
                ldsm_x4_t(vL, vb_l + off);
                mma_bf16(O[2 * dd],     pH, vH[0], vH[1]);
                mma_bf16(O[2 * dd],     pH, vL[0], vL[1]);
                mma_bf16(O[2 * dd],     pL, vH[0], vH[1]);
                {
                    u32 pH2[4] = {pH[2], pH[3], pH[0], pH[1]};
                    // NOTE: A-fragment for upper 8 keys is the same registers; the
                    // mma uses a[0..3] as k16 — pH already spans k16. Use as-is:
                }
                mma_bf16(O[2 * dd + 1], pH, vH[2], vH[3]);
                mma_bf16(O[2 * dd + 1], pH, vL[2], vL[3]);
                mma_bf16(O[2 * dd + 1], pL, vH[2], vH[3]);
            }
        }
        __syncthreads();
    }

    const float inv0 = (z0 > 0.f) ? 1.f / z0 : 0.f;
    const float inv1 = (z1 > 0.f) ? 1.f / z1 : 0.f;
#pragma unroll
    for (int dt = 0; dt < 8; dt++) {
        const int d = 8 * dt + 2 * t;
        const float v0 = O[dt][0] * inv0, v1 = O[dt][1] * inv0;
        const float v2 = O[dt][2] * inv1, v3 = O[dt][3] * inv1;
        const size_t o0 = ((size_t)(b * NS + qw + g)) * ND + h * NDK + d;
        const size_t o1 = ((size_t)(b * NS + qw + g + 8)) * ND + h * NDK + d;
        *(u32*)&g_Ch[o0] = packbf(v0, v1);
        *(u32*)&g_Cl[o0] = packbf(v0 - bfround(v0), v1 - bfround(v1));
        *(u32*)&g_Ch[o1] = packbf(v2, v3);
        *(u32*)&g_Cl[o1] = packbf(v2 - bfround(v2), v3 - bfround(v3));
    }
    if (t == 0) {
        g_M[(size_t)bh * NS + qw + g] = m0r;
        g_M[(size_t)bh * NS + qw + g + 8] = m1r;
        g_Z[(size_t)bh * NS + qw + g] = inv0;
        g_Z[(size_t)bh * NS + qw + g + 8] = inv1;
    }
}

// ---------------------------------------------------------------------------
extern "C" void kernel_launch(void* const* d_in, const int* in_sizes, int n_in,
                              void* d_out, int out_size) {
    const float* qkv[3] = {0, 0, 0};
    const float* Ws[4] = {0, 0, 0, 0};
    const float* bs[4] = {0, 0, 0, 0};
    const void* maskraw = 0;
    int nqkv = 0, nW = 0, nb = 0;
    for (int i = 0; i < n_in; i++) {
        const int sz = in_sizes[i];
        if (sz == NB * NS * ND) { if (nqkv < 3) qkv[nqkv++] = (const float*)d_in[i]; }
        else if (sz == ND * ND) { if (nW < 4) Ws[nW++] = (const float*)d_in[i]; }
        else if (sz == ND)      { if (nb < 4) bs[nb++] = (const float*)d_in[i]; }
        else if (sz == NB * NS) { maskraw = d_in[i]; }
    }
    float* out = (float*)d_out;

    mask_detect<<<1, 256>>>((const unsigned char*)maskraw);
    mask_convert<<<(NB * NS + 255) / 256, 256>>>(maskraw);

    const int nX = NB * NS * ND;
    const int nWel = ND * ND;
    split_in<<<dim3(nX / 4 / 256, 1, 3), 256>>>(qkv[0], qkv[1], qkv[2]);
    split_w<<<dim3(nWel / 4 / 256, 1, 4), 256>>>(Ws[0], Ws[1], Ws[2], Ws[3]);

    proj_qkv<<<dim3(ND / 128, (NB * NS) / 128, 3), 256>>>(bs[0], bs[1], bs[2]);

    cudaFuncSetAttribute(flash_mma, cudaFuncAttributeMaxDynamicSharedMemorySize,
                         (int)FLASH_SMEM);
    flash_mma<<<dim3(NS / 128, NB * NH), 256, FLASH_SMEM>>>();

    proj_out<<<dim3(ND / 128, (NB * NS) / 128), 256>>>(bs[3], out);

    const long long need = (long long)NB * NS * ND + (long long)NB * NS * NS;
    if ((long long)out_size >= need) {
        mean_ew<<<dim3(1, NS, NB), 256>>>(out + (size_t)NB * NS * ND);
    }
}

// round 16
// speedup vs baseline: 1.1613x; 1.1613x over previous
#include <cuda_runtime.h>
#include <cuda_bf16.h>
#include <cuda_fp16.h>
#include <math.h>

#define NB 4
#define NS 2048
#define ND 512
#define NH 8
#define NDK 64
#define LOG2E 1.4426950408889634f
#define SCL2 (0.125f * LOG2E)
#define MINIT (-1e30f)
#define NTILE (NS / 64)

typedef unsigned int u32;
typedef __nv_bfloat16 bf16;

// ---------------- scratch ----------------
__device__ bf16 g_Ah[(size_t)3 * NB * NS * ND];
__device__ bf16 g_Al[(size_t)3 * NB * NS * ND];
__device__ bf16 g_Wh[(size_t)4 * ND * ND];
__device__ bf16 g_Wl[(size_t)4 * ND * ND];
__device__ bf16 g_Qh[(size_t)NB * NH * NS * NDK];
__device__ bf16 g_Ql[(size_t)NB * NH * NS * NDK];
__device__ bf16 g_Kh[(size_t)NB * NH * NS * NDK];
__device__ bf16 g_Kl[(size_t)NB * NH * NS * NDK];
__device__ bf16 g_Vh[(size_t)NB * NH * NS * NDK];
__device__ bf16 g_Vl[(size_t)NB * NH * NS * NDK];
__device__ bf16 g_Ch[(size_t)NB * NS * ND];
__device__ bf16 g_Cl[(size_t)NB * NS * ND];
__device__ float g_M[(size_t)NB * NH * NS];
__device__ float g_Z[(size_t)NB * NH * NS];    // 1/Z
__device__ float g_Mt[(size_t)NB * NH * NTILE * NS];
__device__ float g_madd[(size_t)NB * NS];
__device__ int   g_maskkind;
__device__ u32 g_S[(size_t)NB * NS * NH * NS / 2];  // fp16x2 tile-local probs

// ---------------- helpers ----------------
__device__ __forceinline__ float bfround(float x) {
    return __bfloat162float(__float2bfloat16(x));
}
__device__ __forceinline__ u32 packbf(float lo_el, float hi_el) {
    u32 r;
    asm("cvt.rn.bf16x2.f32 %0, %1, %2;" : "=r"(r) : "f"(hi_el), "f"(lo_el));
    return r;
}
__device__ __forceinline__ u32 packhf(float lo_el, float hi_el) {
    u32 r;
    asm("cvt.rn.f16x2.f32 %0, %1, %2;" : "=r"(r) : "f"(hi_el), "f"(lo_el));
    return r;
}
__device__ __forceinline__ float2 h2f2(u32 v) {
    __half2 h = *(__half2*)&v;
    return __half22float2(h);
}
__device__ __forceinline__ float ex2f(float x) {
    float y;
    asm("ex2.approx.f32 %0, %1;" : "=f"(y) : "f"(x));
    return y;
}
__device__ __forceinline__ void mma_bf16(float d[4], const u32 a[4], u32 b0, u32 b1) {
    asm volatile(
        "mma.sync.aligned.m16n8k16.row.col.f32.bf16.bf16.f32 "
        "{%0,%1,%2,%3}, {%4,%5,%6,%7}, {%8,%9}, {%0,%1,%2,%3};"
        : "+f"(d[0]), "+f"(d[1]), "+f"(d[2]), "+f"(d[3])
        : "r"(a[0]), "r"(a[1]), "r"(a[2]), "r"(a[3]), "r"(b0), "r"(b1));
}
__device__ __forceinline__ u32 smem_u32p(const void* p) {
    u32 a;
    asm("{ .reg .u64 t; cvta.to.shared.u64 t, %1; cvt.u32.u64 %0, t; }" : "=r"(a) : "l"(p));
    return a;
}
__device__ __forceinline__ void ldsm_x4(u32* r, u32 a) {
    asm volatile("ldmatrix.sync.aligned.m8n8.x4.shared.b16 {%0,%1,%2,%3}, [%4];"
                 : "=r"(r[0]), "=r"(r[1]), "=r"(r[2]), "=r"(r[3]) : "r"(a));
}
__device__ __forceinline__ void ldsm_x4_t(u32* r, u32 a) {
    asm volatile("ldmatrix.sync.aligned.m8n8.x4.trans.shared.b16 {%0,%1,%2,%3}, [%4];"
                 : "=r"(r[0]), "=r"(r[1]), "=r"(r[2]), "=r"(r[3]) : "r"(a));
}
__device__ __forceinline__ void cp16(u32 smem_addr, const void* gptr) {
    asm volatile("cp.async.cg.shared.global [%0], [%1], 16;"
                 :: "r"(smem_addr), "l"(gptr) : "memory");
}
#define CP_COMMIT() asm volatile("cp.async.commit_group;" ::: "memory")
#define CP_WAIT0()  asm volatile("cp.async.wait_group 0;" ::: "memory")

// ---------------- mask sniff / convert (validated R2) ----------------
__global__ void mask_detect(const unsigned char* __restrict__ mraw) {
    __shared__ int s_not01, s_oneOther, s_3fOdd;
    if (threadIdx.x == 0) { s_not01 = 0; s_oneOther = 0; s_3fOdd = 0; }
    __syncthreads();
    int l_not01 = 0, l_oneOther = 0, l_3fOdd = 0;
    for (int i = threadIdx.x; i < NB * NS; i += blockDim.x) {
        const unsigned char v = mraw[i];
        if (v > 1) l_not01++;
        if (v == 1 && (i & 3) != 0) l_oneOther++;
        if (v == 0x3f && (i & 3) == 1) l_3fOdd++;
    }
    atomicAdd(&s_not01, l_not01);
    atomicAdd(&s_oneOther, l_oneOther);
    atomicAdd(&s_3fOdd, l_3fOdd);
    __syncthreads();
    if (threadIdx.x == 0) {
        int kind;
        if (s_not01 > 0)          kind = (s_3fOdd > 0) ? 3 : 2;
        else if (s_oneOther == 0) kind = 1;
        else                      kind = 0;
        g_maskkind = kind;
    }
}

__global__ void mask_convert(const void* __restrict__ mraw) {
    const int i = blockIdx.x * blockDim.x + threadIdx.x;
    if (i >= NB * NS) return;
    const int kind = g_maskkind;
    bool on;
    if (kind == 0)      on = ((const unsigned char*)mraw)[i] != 0;
    else if (kind == 1) on = ((const int*)mraw)[i] != 0;
    else if (kind == 2) on = ((const float*)mraw)[i] != 0.f;
    else                on = ((const unsigned short*)mraw)[i] != 0;
    g_madd[i] = on ? 0.f : -INFINITY;
}

// ---------------- splits ----------------
__global__ void split_in(const float* __restrict__ s0, const float* __restrict__ s1,
                         const float* __restrict__ s2) {
    const int z = blockIdx.z;
    const float* s = (z == 0) ? s0 : (z == 1) ? s1 : s2;
    bf16* h = g_Ah + (size_t)z * NB * NS * ND;
    bf16* l = g_Al + (size_t)z * NB * NS * ND;
    const int i = (blockIdx.x * blockDim.x + threadIdx.x) * 4;
    float4 v = *(const float4*)&s[i];
    uint2 hh, ll;
    hh.x = packbf(v.x, v.y);
    hh.y = packbf(v.z, v.w);
    ll.x = packbf(v.x - bfround(v.x), v.y - bfround(v.y));
    ll.y = packbf(v.z - bfround(v.z), v.w - bfround(v.w));
    *(uint2*)&h[i] = hh;
    *(uint2*)&l[i] = ll;
}

__global__ void split_w(const float* __restrict__ s0, const float* __restrict__ s1,
                        const float* __restrict__ s2, const float* __restrict__ s3) {
    const int z = blockIdx.z;
    const float* s = (z == 0) ? s0 : (z == 1) ? s1 : (z == 2) ? s2 : s3;
    bf16* h = g_Wh + (size_t)z * ND * ND;
    bf16* l = g_Wl + (size_t)z * ND * ND;
    const int i = (blockIdx.x * blockDim.x + threadIdx.x) * 4;
    float4 v = *(const float4*)&s[i];
    uint2 hh, ll;
    hh.x = packbf(v.x, v.y);
    hh.y = packbf(v.z, v.w);
    ll.x = packbf(v.x - bfround(v.x), v.y - bfround(v.y));
    ll.y = packbf(v.z - bfround(v.z), v.w - bfround(v.w));
    *(uint2*)&h[i] = hh;
    *(uint2*)&l[i] = ll;
}

// ---------------------------------------------------------------------------
// QKV projections (R12 plain-LDS version). grid (ND/128, M/128, 3), 256 thr.
// ---------------------------------------------------------------------------
__global__ __launch_bounds__(256) void proj_qkv(const float* __restrict__ b0p,
                                                const float* __restrict__ b1p,
                                                const float* __restrict__ b2p) {
    __shared__ __align__(16) bf16 Xsh[128 * 40], Xsl[128 * 40];
    __shared__ __align__(16) bf16 Wsh[128 * 40], Wsl[128 * 40];

    const int z = blockIdx.z;
    const bf16* Xh = g_Ah + (size_t)z * NB * NS * ND;
    const bf16* Xl = g_Al + (size_t)z * NB * NS * ND;
    const bf16* Wh = g_Wh + (size_t)z * ND * ND;
    const bf16* Wl = g_Wl + (size_t)z * ND * ND;
    const float* bias = (z == 0) ? b0p : (z == 1) ? b1p : b2p;
    bf16* Yh = (z == 0) ? g_Qh : (z == 1) ? g_Kh : g_Vh;
    bf16* Yl = (z == 0) ? g_Ql : (z == 1) ? g_Kl : g_Vl;

    const int tid = threadIdx.x;
    const int w = tid >> 5, lane = tid & 31, g = lane >> 2, t = lane & 3;
    const int m0 = blockIdx.y * 128, n0 = blockIdx.x * 128;
    const int mw = (w >> 1) * 32, nw = (w & 1) * 64;

    float D[2][8][4];
#pragma unroll
    for (int mi = 0; mi < 2; mi++)
#pragma unroll
        for (int nt = 0; nt < 8; nt++)
#pragma unroll
            for (int j = 0; j < 4; j++) D[mi][nt][j] = 0.f;

    const int lrow = tid >> 2, lcol = (tid & 3) * 8;

    for (int k0 = 0; k0 < ND; k0 += 32) {
#pragma unroll
        for (int p = 0; p < 2; p++) {
            const int row = lrow + 64 * p;
            *(uint4*)&Xsh[row * 40 + lcol] = *(const uint4*)&Xh[(size_t)(m0 + row) * ND + k0 + lcol];
            *(uint4*)&Xsl[row * 40 + lcol] = *(const uint4*)&Xl[(size_t)(m0 + row) * ND + k0 + lcol];
            *(uint4*)&Wsh[row * 40 + lcol] = *(const uint4*)&Wh[(size_t)(n0 + row) * ND + k0 + lcol];
            *(uint4*)&Wsl[row * 40 + lcol] = *(const uint4*)&Wl[(size_t)(n0 + row) * ND + k0 + lcol];
        }
        __syncthreads();

        const u32* XH = (const u32*)Xsh;
        const u32* XL = (const u32*)Xsl;
        const u32* WH = (const u32*)Wsh;
        const u32* WL = (const u32*)Wsl;
#pragma unroll
        for (int c = 0; c < 2; c++) {
            u32 aH[2][4], aL[2][4];
#pragma unroll
            for (int mi = 0; mi < 2; mi++) {
                const int r0 = (mw + 16 * mi + g) * 20 + 8 * c + t;
                const int r1 = (mw + 16 * mi + g + 8) * 20 + 8 * c + t;
                aH[mi][0] = XH[r0]; aH[mi][1] = XH[r1];
                aH[mi][2] = XH[r0 + 4]; aH[mi][3] = XH[r1 + 4];
                aL[mi][0] = XL[r0]; aL[mi][1] = XL[r1];
                aL[mi][2] = XL[r0 + 4]; aL[mi][3] = XL[r1 + 4];
            }
#pragma unroll
            for (int nt = 0; nt < 8; nt++) {
                const int nb = (nw + 8 * nt + g) * 20 + 8 * c + t;
                const u32 bh0 = WH[nb], bh1 = WH[nb + 4];
                const u32 bl0 = WL[nb], bl1 = WL[nb + 4];
#pragma unroll
                for (int mi = 0; mi < 2; mi++) {
                    mma_bf16(D[mi][nt], aH[mi], bh0, bh1);
                    mma_bf16(D[mi][nt], aH[mi], bl0, bl1);
                    mma_bf16(D[mi][nt], aL[mi], bh0, bh1);
                }
            }
        }
        __syncthreads();
    }

#pragma unroll
    for (int mi = 0; mi < 2; mi++) {
#pragma unroll
        for (int nt = 0; nt < 8; nt++) {
            const int n = n0 + nw + 8 * nt + 2 * t;
            const float bb0 = bias[n], bb1 = bias[n + 1];
            const int h = n >> 6, dk = n & 63;
#pragma unroll
            for (int rr = 0; rr < 2; rr++) {
                const int m = m0 + mw + 16 * mi + g + 8 * rr;
                const float v0 = D[mi][nt][2 * rr + 0] + bb0;
                const float v1 = D[mi][nt][2 * rr + 1] + bb1;
                const int b = m >> 11, s = m & (NS - 1);
                const size_t off = (((size_t)(b * NH + h)) * NS + s) * NDK + dk;
                *(u32*)&Yh[off] = packbf(v0, v1);
                *(u32*)&Yl[off] = packbf(v0 - bfround(v0), v1 - bfround(v1));
            }
        }
    }
}

// ---------------------------------------------------------------------------
// Output projection (R12 plain-LDS version)
// ---------------------------------------------------------------------------
__global__ __launch_bounds__(256) void proj_out(const float* __restrict__ bias,
                                                float* __restrict__ out) {
    __shared__ __align__(16) bf16 Xsh[128 * 40], Xsl[128 * 40];
    __shared__ __align__(16) bf16 Wsh[128 * 40], Wsl[128 * 40];

    const bf16* Xh = g_Ch;
    const bf16* Xl = g_Cl;
    const bf16* Wh = g_Wh + (size_t)3 * ND * ND;
    const bf16* Wl = g_Wl + (size_t)3 * ND * ND;

    const int tid = threadIdx.x;
    const int w = tid >> 5, lane = tid & 31, g = lane >> 2, t = lane & 3;
    const int m0 = blockIdx.y * 128, n0 = blockIdx.x * 128;
    const int mw = (w >> 1) * 32, nw = (w & 1) * 64;

    float D[2][8][4];
#pragma unroll
    for (int mi = 0; mi < 2; mi++)
#pragma unroll
        for (int nt = 0; nt < 8; nt++)
#pragma unroll
            for (int j = 0; j < 4; j++) D[mi][nt][j] = 0.f;

    const int lrow = tid >> 2, lcol = (tid & 3) * 8;

    for (int k0 = 0; k0 < ND; k0 += 32) {
#pragma unroll
        for (int p = 0; p < 2; p++) {
            const int row = lrow + 64 * p;
            *(uint4*)&Xsh[row * 40 + lcol] = *(const uint4*)&Xh[(size_t)(m0 + row) * ND + k0 + lcol];
            *(uint4*)&Xsl[row * 40 + lcol] = *(const uint4*)&Xl[(size_t)(m0 + row) * ND + k0 + lcol];
            *(uint4*)&Wsh[row * 40 + lcol] = *(const uint4*)&Wh[(size_t)(n0 + row) * ND + k0 + lcol];
            *(uint4*)&Wsl[row * 40 + lcol] = *(const uint4*)&Wl[(size_t)(n0 + row) * ND + k0 + lcol];
        }
        __syncthreads();

        const u32* XH = (const u32*)Xsh;
        const u32* XL = (const u32*)Xsl;
        const u32* WH = (const u32*)Wsh;
        const u32* WL = (const u32*)Wsl;
#pragma unroll
        for (int c = 0; c < 2; c++) {
            u32 aH[2][4], aL[2][4];
#pragma unroll
            for (int mi = 0; mi < 2; mi++) {
                const int r0 = (mw + 16 * mi + g) * 20 + 8 * c + t;
                const int r1 = (mw + 16 * mi + g + 8) * 20 + 8 * c + t;
                aH[mi][0] = XH[r0]; aH[mi][1] = XH[r1];
                aH[mi][2] = XH[r0 + 4]; aH[mi][3] = XH[r1 + 4];
                aL[mi][0] = XL[r0]; aL[mi][1] = XL[r1];
                aL[mi][2] = XL[r0 + 4]; aL[mi][3] = XL[r1 + 4];
            }
#pragma unroll
            for (int nt = 0; nt < 8; nt++) {
                const int nb = (nw + 8 * nt + g) * 20 + 8 * c + t;
                const u32 bh0 = WH[nb], bh1 = WH[nb + 4];
                const u32 bl0 = WL[nb], bl1 = WL[nb + 4];
#pragma unroll
                for (int mi = 0; mi < 2; mi++) {
                    mma_bf16(D[mi][nt], aH[mi], bh0, bh1);
                    mma_bf16(D[mi][nt], aH[mi], bl0, bl1);
                    mma_bf16(D[mi][nt], aL[mi], bh0, bh1);
                }
            }
        }
        __syncthreads();
    }

#pragma unroll
    for (int mi = 0; mi < 2; mi++) {
#pragma unroll
        for (int nt = 0; nt < 8; nt++) {
            const int n = n0 + nw + 8 * nt + 2 * t;
            const float bb0 = bias[n], bb1 = bias[n + 1];
#pragma unroll
            for (int rr = 0; rr < 2; rr++) {
                const int m = m0 + mw + 16 * mi + g + 8 * rr;
                float2 v = make_float2(D[mi][nt][2 * rr + 0] + bb0,
                                       D[mi][nt][2 * rr + 1] + bb1);
                *(float2*)&out[(size_t)m * ND + n] = v;
            }
        }
    }
}

// ---------------------------------------------------------------------------
// attn.mean (R12 structure, tile = k>>6 for KT=64)
// ---------------------------------------------------------------------------
__global__ __launch_bounds__(256) void mean_ew(float* __restrict__ out) {
    const int b = blockIdx.z;
    const int q = blockIdx.y;
    const int k = threadIdx.x * 8;
    const int tile = k >> 6;

    const u32* Pbase = g_S + (((size_t)(b * NS + q) * NH) * NS + k >> 1);
    float acc[8];
#pragma unroll
    for (int j = 0; j < 8; j++) acc[j] = 0.f;

#pragma unroll
    for (int h = 0; h < NH; h++) {
        const size_t bh = (size_t)(b * NH + h);
        const float m = g_M[bh * NS + q];
        const float zi = g_Z[bh * NS + q];
        const float mt = g_Mt[(bh * NTILE + tile) * NS + q];
        const float corr = ex2f(mt - m) * zi;
        uint4 pv = *(const uint4*)&Pbase[(size_t)h * (NS >> 1)];
        float2 p0 = h2f2(pv.x), p1 = h2f2(pv.y), p2 = h2f2(pv.z), p3 = h2f2(pv.w);
        acc[0] += p0.x * corr; acc[1] += p0.y * corr;
        acc[2] += p1.x * corr; acc[3] += p1.y * corr;
        acc[4] += p2.x * corr; acc[5] += p2.y * corr;
        acc[6] += p3.x * corr; acc[7] += p3.y * corr;
    }
    float4 oA = make_float4(acc[0] * 0.125f, acc[1] * 0.125f, acc[2] * 0.125f, acc[3] * 0.125f);
    float4 oB = make_float4(acc[4] * 0.125f, acc[5] * 0.125f, acc[6] * 0.125f, acc[7] * 0.125f);
    float* orow = &out[((size_t)(b * NS + q)) * NS + k];
    *(float4*)&orow[0] = oA;
    *(float4*)&orow[4] = oB;
}

// ---------------------------------------------------------------------------
// Flash attention: R12 structure (128q x 64k, 2 CTAs/SM) with cp.async staging.
// ---------------------------------------------------------------------------
__global__ __launch_bounds__(256, 2) void flash_mma() {
    __shared__ __align__(16) bf16 Khs[64 * 72], Kls[64 * 72];
    __shared__ __align__(16) bf16 Vhs[64 * 72], Vls[64 * 72];
    __shared__ float madds[64];

    const int tid = threadIdx.x;
    const int w = tid >> 5, lane = tid & 31, g = lane >> 2, t = lane & 3;
    const int bh = blockIdx.y;
    const int b = bh >> 3, h = bh & 7;
    const int q0 = blockIdx.x * 128;
    const int qw = q0 + 16 * w;

    const bf16* Qhp = g_Qh + (size_t)bh * NS * NDK;
    const bf16* Qlp = g_Ql + (size_t)bh * NS * NDK;
    const bf16* Khp = g_Kh + (size_t)bh * NS * NDK;
    const bf16* Klp = g_Kl + (size_t)bh * NS * NDK;
    const bf16* Vhp = g_Vh + (size_t)bh * NS * NDK;
    const bf16* Vlp = g_Vl + (size_t)bh * NS * NDK;

    u32* Srow0 = g_S + (((size_t)(b * NS + qw + g) * NH + h) * NS >> 1);
    u32* Srow1 = g_S + (((size_t)(b * NS + qw + g + 8) * NH + h) * NS >> 1);

    const u32 kb_h = smem_u32p(Khs), kb_l = smem_u32p(Kls);
    const u32 vb_h = smem_u32p(Vhs), vb_l = smem_u32p(Vls);
    const u32 aoffK = ((lane & 7) * 72 + 8 * (lane >> 3)) * 2;
    const u32 aoffV = (((lane & 7) + 8 * ((lane >> 3) & 1)) * 72 + 8 * (lane >> 4)) * 2;

    u32 qH[4][4], qL[4][4];
#pragma unroll
    for (int c = 0; c < 4; c++) {
        const size_t r0 = (size_t)(qw + g) * NDK + 16 * c + 2 * t;
        const size_t r1 = (size_t)(qw + g + 8) * NDK + 16 * c + 2 * t;
        qH[c][0] = *(const u32*)&Qhp[r0]; qH[c][1] = *(const u32*)&Qhp[r1];
        qH[c][2] = *(const u32*)&Qhp[r0 + 8]; qH[c][3] = *(const u32*)&Qhp[r1 + 8];
        qL[c][0] = *(const u32*)&Qlp[r0]; qL[c][1] = *(const u32*)&Qlp[r1];
        qL[c][2] = *(const u32*)&Qlp[r0 + 8]; qL[c][3] = *(const u32*)&Qlp[r1 + 8];
    }

    float O[8][4];
#pragma unroll
    for (int dt = 0; dt < 8; dt++)
#pragma unroll
        for (int j = 0; j < 4; j++) O[dt][j] = 0.f;
    float m0r = MINIT, m1r = MINIT, z0 = 0.f, z1 = 0.f;

    const int srow = tid >> 3, sseg = tid & 7;

    for (int kt = 0; kt < NS; kt += 64) {
        // ---- stage K and V via cp.async (no register round-trip) ----
#pragma unroll
        for (int p = 0; p < 2; p++) {
            const int row = srow + 32 * p;
            const size_t go = (size_t)(kt + row) * NDK + sseg * 8;
            const u32 so = (u32)(row * 72 + sseg * 8) * 2;
            cp16(kb_h + so, &Khp[go]);
            cp16(kb_l + so, &Klp[go]);
            cp16(vb_h + so, &Vhp[go]);
            cp16(vb_l + so, &Vlp[go]);
        }
        CP_COMMIT();
        if (tid < 64) madds[tid] = g_madd[b * NS + kt + tid];
        CP_WAIT0();
        __syncthreads();

        // ---- S = Q K^T (K fragments via ldmatrix.x4) ----
        float S[8][4];
#pragma unroll
        for (int nt = 0; nt < 8; nt++)
#pragma unroll
            for (int j = 0; j < 4; j++) S[nt][j] = 0.f;
#pragma unroll
        for (int nt = 0; nt < 8; nt++) {
#pragma unroll
            for (int cc = 0; cc < 2; cc++) {
                const u32 off = aoffK + (u32)(8 * nt * 72 + 32 * cc) * 2;
                u32 fH[4], fL[4];
                ldsm_x4(fH, kb_h + off);
                ldsm_x4(fL, kb_l + off);
                mma_bf16(S[nt], qH[2 * cc],     fH[0], fH[1]);
                mma_bf16(S[nt], qH[2 * cc],     fL[0], fL[1]);
                mma_bf16(S[nt], qL[2 * cc],     fH[0], fH[1]);
                mma_bf16(S[nt], qH[2 * cc + 1], fH[2], fH[3]);
                mma_bf16(S[nt], qH[2 * cc + 1], fL[2], fL[3]);
                mma_bf16(S[nt], qL[2 * cc + 1], fH[2], fH[3]);
            }
        }

        // ---- scale + mask, log2-domain online softmax ----
        float rm0 = MINIT, rm1 = MINIT;
#pragma unroll
        for (int nt = 0; nt < 8; nt++) {
            const float ma = madds[8 * nt + 2 * t], mb = madds[8 * nt + 2 * t + 1];
            S[nt][0] = S[nt][0] * SCL2 + ma; S[nt][1] = S[nt][1] * SCL2 + mb;
            S[nt][2] = S[nt][2] * SCL2 + ma; S[nt][3] = S[nt][3] * SCL2 + mb;
            rm0 = fmaxf(rm0, fmaxf(S[nt][0], S[nt][1]));
            rm1 = fmaxf(rm1, fmaxf(S[nt][2], S[nt][3]));
        }
        rm0 = fmaxf(rm0, __shfl_xor_sync(0xffffffffu, rm0, 1));
        rm0 = fmaxf(rm0, __shfl_xor_sync(0xffffffffu, rm0, 2));
        rm1 = fmaxf(rm1, __shfl_xor_sync(0xffffffffu, rm1, 1));
        rm1 = fmaxf(rm1, __shfl_xor_sync(0xffffffffu, rm1, 2));
        const float mn0 = fmaxf(m0r, rm0), mn1 = fmaxf(m1r, rm1);
        const float al0 = ex2f(m0r - mn0);
        const float al1 = ex2f(m1r - mn1);
        if (t == 0) {
            const size_t mtb = ((size_t)bh * NTILE + (kt >> 6)) * NS;
            g_Mt[mtb + qw + g] = mn0;
            g_Mt[mtb + qw + g + 8] = mn1;
        }
        float rs0 = 0.f, rs1 = 0.f;
#pragma unroll
        for (int nt = 0; nt < 8; nt++) {
            const float p0 = ex2f(S[nt][0] - mn0);
            const float p1 = ex2f(S[nt][1] - mn0);
            const float p2 = ex2f(S[nt][2] - mn1);
            const float p3 = ex2f(S[nt][3] - mn1);
            S[nt][0] = p0; S[nt][1] = p1; S[nt][2] = p2; S[nt][3] = p3;
            const int col2 = (kt + 8 * nt + 2 * t) >> 1;
            Srow0[col2] = packhf(p0, p1);
            Srow1[col2] = packhf(p2, p3);
            rs0 += p0 + p1; rs1 += p2 + p3;
        }
        rs0 += __shfl_xor_sync(0xffffffffu, rs0, 1);
        rs0 += __shfl_xor_sync(0xffffffffu, rs0, 2);
        rs1 += __shfl_xor_sync(0xffffffffu, rs1, 1);
        rs1 += __shfl_xor_sync(0xffffffffu, rs1, 2);
        z0 = z0 * al0 + rs0; z1 = z1 * al1 + rs1;
        m0r = mn0; m1r = mn1;
#pragma unroll
        for (int dt = 0; dt < 8; dt++) {
            O[dt][0] *= al0; O[dt][1] *= al0;
            O[dt][2] *= al1; O[dt][3] *= al1;
        }

        u32 pH[4][4], pL[4][4];
#pragma unroll
        for (int c = 0; c < 4; c++) {
            const float a0 = S[2 * c][0],     a1 = S[2 * c][1];
            const float a2 = S[2 * c][2],     a3 = S[2 * c][3];
            const float b0 = S[2 * c + 1][0], b1 = S[2 * c + 1][1];
            const float b2 = S[2 * c + 1][2], b3 = S[2 * c + 1][3];
            pH[c][0] = packbf(a0, a1); pH[c][1] = packbf(a2, a3);
            pH[c][2] = packbf(b0, b1); pH[c][3] = packbf(b2, b3);
            pL[c][0] = packbf(a0 - bfround(a0), a1 - bfround(a1));
            pL[c][1] = packbf(a2 - bfround(a2), a3 - bfround(a3));
            pL[c][2] = packbf(b0 - bfround(b0), b1 - bfround(b1));
            pL[c][3] = packbf(b2 - bfround(b2), b3 - bfround(b3));
        }

#pragma unroll
        for (int c = 0; c < 4; c++) {
#pragma unroll
            for (int dd = 0; dd < 4; dd++) {
                const u32 off = aoffV + (u32)(16 * c * 72 + 16 * dd) * 2;
                u32 vH[4], vL[4];
                ldsm_x4_t(vH, vb_h + off);
                ldsm_x4_t(vL, vb_l + off);
                mma_bf16(O[2 * dd],     pH[c], vH[0], vH[1]);
                mma_bf16(O[2 * dd],     pH[c], vL[0], vL[1]);
                mma_bf16(O[2 * dd],     pL[c], vH[0], vH[1]);
                mma_bf16(O[2 * dd + 1], pH[c], vH[2], vH[3]);
                mma_bf16(O[2 * dd + 1], pH[c], vL[2], vL[3]);
                mma_bf16(O[2 * dd + 1], pL[c], vH[2], vH[3]);
            }
        }
        __syncthreads();
    }

    const float inv0 = (z0 > 0.f) ? 1.f / z0 : 0.f;
    const float inv1 = (z1 > 0.f) ? 1.f / z1 : 0.f;
#pragma unroll
    for (int dt = 0; dt < 8; dt++) {
        const int d = 8 * dt + 2 * t;
        const float v0 = O[dt][0] * inv0, v1 = O[dt][1] * inv0;
        const float v2 = O[dt][2] * inv1, v3 = O[dt][3] * inv1;
        const size_t o0 = ((size_t)(b * NS + qw + g)) * ND + h * NDK + d;
        const size_t o1 = ((size_t)(b * NS + qw + g + 8)) * ND + h * NDK + d;
        *(u32*)&g_Ch[o0] = packbf(v0, v1);
        *(u32*)&g_Cl[o0] = packbf(v0 - bfround(v0), v1 - bfround(v1));
        *(u32*)&g_Ch[o1] = packbf(v2, v3);
        *(u32*)&g_Cl[o1] = packbf(v2 - bfround(v2), v3 - bfround(v3));
    }
    if (t == 0) {
        g_M[(size_t)bh * NS + qw + g] = m0r;
        g_M[(size_t)bh * NS + qw + g + 8] = m1r;
        g_Z[(size_t)bh * NS + qw + g] = inv0;
        g_Z[(size_t)bh * NS + qw + g + 8] = inv1;
    }
}

// ---------------------------------------------------------------------------
extern "C" void kernel_launch(void* const* d_in, const int* in_sizes, int n_in,
                              void* d_out, int out_size) {
    const float* qkv[3] = {0, 0, 0};
    const float* Ws[4] = {0, 0, 0, 0};
    const float* bs[4] = {0, 0, 0, 0};
    const void* maskraw = 0;
    int nqkv = 0, nW = 0, nb = 0;
    for (int i = 0; i < n_in; i++) {
        const int sz = in_sizes[i];
        if (sz == NB * NS * ND) { if (nqkv < 3) qkv[nqkv++] = (const float*)d_in[i]; }
        else if (sz == ND * ND) { if (nW < 4) Ws[nW++] = (const float*)d_in[i]; }
        else if (sz == ND)      { if (nb < 4) bs[nb++] = (const float*)d_in[i]; }
        else if (sz == NB * NS) { maskraw = d_in[i]; }
    }
    float* out = (float*)d_out;

    mask_detect<<<1, 256>>>((const unsigned char*)maskraw);
    mask_convert<<<(NB * NS + 255) / 256, 256>>>(maskraw);

    const int nX = NB * NS * ND;
    const int nWel = ND * ND;
    split_in<<<dim3(nX / 4 / 256, 1, 3), 256>>>(qkv[0], qkv[1], qkv[2]);
    split_w<<<dim3(nWel / 4 / 256, 1, 4), 256>>>(Ws[0], Ws[1], Ws[2], Ws[3]);

    proj_qkv<<<dim3(ND / 128, (NB * NS) / 128, 3), 256>>>(bs[0], bs[1], bs[2]);

    flash_mma<<<dim3(NS / 128, NB * NH), 256>>>();

    proj_out<<<dim3(ND / 128, (NB * NS) / 128), 256>>>(bs[3], out);

    const long long need = (long long)NB * NS * ND + (long long)NB * NS * NS;
    if ((long long)out_size >= need) {
        mean_ew<<<dim3(1, NS, NB), 256>>>(out + (size_t)NB * NS * ND);
    }
}

// round 17
// speedup vs baseline: 1.1630x; 1.0015x over previous
#include <cuda_runtime.h>
#include <cuda_bf16.h>
#include <cuda_fp16.h>
#include <math.h>

#define NB 4
#define NS 2048
#define ND 512
#define NH 8
#define NDK 64
#define LOG2E 1.4426950408889634f
#define SCL2 (0.125f * LOG2E)
#define MINIT (-1e30f)
#define NTILE (NS / 64)

typedef unsigned int u32;
typedef __nv_bfloat16 bf16;

// ---------------- scratch ----------------
__device__ bf16 g_Wh[(size_t)4 * ND * ND];
__device__ bf16 g_Wl[(size_t)4 * ND * ND];
__device__ bf16 g_Qh[(size_t)NB * NH * NS * NDK];
__device__ bf16 g_Ql[(size_t)NB * NH * NS * NDK];
__device__ bf16 g_Kh[(size_t)NB * NH * NS * NDK];
__device__ bf16 g_Kl[(size_t)NB * NH * NS * NDK];
__device__ bf16 g_Vh[(size_t)NB * NH * NS * NDK];
__device__ bf16 g_Vl[(size_t)NB * NH * NS * NDK];
__device__ bf16 g_Ch[(size_t)NB * NS * ND];
__device__ bf16 g_Cl[(size_t)NB * NS * ND];
__device__ float g_M[(size_t)NB * NH * NS];
__device__ float g_Z[(size_t)NB * NH * NS];    // 1/Z
__device__ float g_Mt[(size_t)NB * NH * NTILE * NS];
__device__ float g_madd[(size_t)NB * NS];
__device__ int   g_maskkind;
__device__ u32 g_S[(size_t)NB * NS * NH * NS / 2];  // fp16x2 tile-local probs

// ---------------- helpers ----------------
__device__ __forceinline__ float bfround(float x) {
    return __bfloat162float(__float2bfloat16(x));
}
__device__ __forceinline__ u32 packbf(float lo_el, float hi_el) {
    u32 r;
    asm("cvt.rn.bf16x2.f32 %0, %1, %2;" : "=r"(r) : "f"(hi_el), "f"(lo_el));
    return r;
}
__device__ __forceinline__ u32 packhf(float lo_el, float hi_el) {
    u32 r;
    asm("cvt.rn.f16x2.f32 %0, %1, %2;" : "=r"(r) : "f"(hi_el), "f"(lo_el));
    return r;
}
__device__ __forceinline__ float2 h2f2(u32 v) {
    __half2 h = *(__half2*)&v;
    return __half22float2(h);
}
__device__ __forceinline__ float ex2f(float x) {
    float y;
    asm("ex2.approx.f32 %0, %1;" : "=f"(y) : "f"(x));
    return y;
}
__device__ __forceinline__ void mma_bf16(float d[4], const u32 a[4], u32 b0, u32 b1) {
    asm volatile(
        "mma.sync.aligned.m16n8k16.row.col.f32.bf16.bf16.f32 "
        "{%0,%1,%2,%3}, {%4,%5,%6,%7}, {%8,%9}, {%0,%1,%2,%3};"
        : "+f"(d[0]), "+f"(d[1]), "+f"(d[2]), "+f"(d[3])
        : "r"(a[0]), "r"(a[1]), "r"(a[2]), "r"(a[3]), "r"(b0), "r"(b1));
}
__device__ __forceinline__ u32 smem_u32p(const void* p) {
    u32 a;
    asm("{ .reg .u64 t; cvta.to.shared.u64 t, %1; cvt.u32.u64 %0, t; }" : "=r"(a) : "l"(p));
    return a;
}
__device__ __forceinline__ void ldsm_x4(u32* r, u32 a) {
    asm volatile("ldmatrix.sync.aligned.m8n8.x4.shared.b16 {%0,%1,%2,%3}, [%4];"
                 : "=r"(r[0]), "=r"(r[1]), "=r"(r[2]), "=r"(r[3]) : "r"(a));
}
__device__ __forceinline__ void ldsm_x4_t(u32* r, u32 a) {
    asm volatile("ldmatrix.sync.aligned.m8n8.x4.trans.shared.b16 {%0,%1,%2,%3}, [%4];"
                 : "=r"(r[0]), "=r"(r[1]), "=r"(r[2]), "=r"(r[3]) : "r"(a));
}
__device__ __forceinline__ void cp16(u32 smem_addr, const void* gptr) {
    asm volatile("cp.async.cg.shared.global [%0], [%1], 16;"
                 :: "r"(smem_addr), "l"(gptr) : "memory");
}
#define CP_COMMIT() asm volatile("cp.async.commit_group;" ::: "memory")
#define CP_WAIT0()  asm volatile("cp.async.wait_group 0;" ::: "memory")

// ---------------- mask sniff / convert (validated R2) ----------------
__global__ void mask_detect(const unsigned char* __restrict__ mraw) {
    __shared__ int s_not01, s_oneOther, s_3fOdd;
    if (threadIdx.x == 0) { s_not01 = 0; s_oneOther = 0; s_3fOdd = 0; }
    __syncthreads();
    int l_not01 = 0, l_oneOther = 0, l_3fOdd = 0;
    for (int i = threadIdx.x; i < NB * NS; i += blockDim.x) {
        const unsigned char v = mraw[i];
        if (v > 1) l_not01++;
        if (v == 1 && (i & 3) != 0) l_oneOther++;
        if (v == 0x3f && (i & 3) == 1) l_3fOdd++;
    }
    atomicAdd(&s_not01, l_not01);
    atomicAdd(&s_oneOther, l_oneOther);
    atomicAdd(&s_3fOdd, l_3fOdd);
    __syncthreads();
    if (threadIdx.x == 0) {
        int kind;
        if (s_not01 > 0)          kind = (s_3fOdd > 0) ? 3 : 2;
        else if (s_oneOther == 0) kind = 1;
        else                      kind = 0;
        g_maskkind = kind;
    }
}

__global__ void mask_convert(const void* __restrict__ mraw) {
    const int i = blockIdx.x * blockDim.x + threadIdx.x;
    if (i >= NB * NS) return;
    const int kind = g_maskkind;
    bool on;
    if (kind == 0)      on = ((const unsigned char*)mraw)[i] != 0;
    else if (kind == 1) on = ((const int*)mraw)[i] != 0;
    else if (kind == 2) on = ((const float*)mraw)[i] != 0.f;
    else                on = ((const unsigned short*)mraw)[i] != 0;
    g_madd[i] = on ? 0.f : -INFINITY;
}

// ---------------- weight split (inputs now split in-kernel) ----------------
__global__ void split_w(const float* __restrict__ s0, const float* __restrict__ s1,
                        const float* __restrict__ s2, const float* __restrict__ s3) {
    const int z = blockIdx.z;
    const float* s = (z == 0) ? s0 : (z == 1) ? s1 : (z == 2) ? s2 : s3;
    bf16* h = g_Wh + (size_t)z * ND * ND;
    bf16* l = g_Wl + (size_t)z * ND * ND;
    const int i = (blockIdx.x * blockDim.x + threadIdx.x) * 4;
    float4 v = *(const float4*)&s[i];
    uint2 hh, ll;
    hh.x = packbf(v.x, v.y);
    hh.y = packbf(v.z, v.w);
    ll.x = packbf(v.x - bfround(v.x), v.y - bfround(v.y));
    ll.y = packbf(v.z - bfround(v.z), v.w - bfround(v.w));
    *(uint2*)&h[i] = hh;
    *(uint2*)&l[i] = ll;
}

// ---------------------------------------------------------------------------
// QKV projections: fp32 X read directly, split into (hi,lo) smem during
// staging (eliminates the split_in kernel + 200MB DRAM round-trip).
// grid (ND/128, M/128, 3), 256 thr.
// ---------------------------------------------------------------------------
__global__ __launch_bounds__(256) void proj_qkv(const float* __restrict__ x0,
                                                const float* __restrict__ x1,
                                                const float* __restrict__ x2,
                                                const float* __restrict__ b0p,
                                                const float* __restrict__ b1p,
                                                const float* __restrict__ b2p) {
    __shared__ __align__(16) bf16 Xsh[128 * 40], Xsl[128 * 40];
    __shared__ __align__(16) bf16 Wsh[128 * 40], Wsl[128 * 40];

    const int z = blockIdx.z;
    const float* X = (z == 0) ? x0 : (z == 1) ? x1 : x2;
    const bf16* Wh = g_Wh + (size_t)z * ND * ND;
    const bf16* Wl = g_Wl + (size_t)z * ND * ND;
    const float* bias = (z == 0) ? b0p : (z == 1) ? b1p : b2p;
    bf16* Yh = (z == 0) ? g_Qh : (z == 1) ? g_Kh : g_Vh;
    bf16* Yl = (z == 0) ? g_Ql : (z == 1) ? g_Kl : g_Vl;

    const int tid = threadIdx.x;
    const int w = tid >> 5, lane = tid & 31, g = lane >> 2, t = lane & 3;
    const int m0 = blockIdx.y * 128, n0 = blockIdx.x * 128;
    const int mw = (w >> 1) * 32, nw = (w & 1) * 64;

    float D[2][8][4];
#pragma unroll
    for (int mi = 0; mi < 2; mi++)
#pragma unroll
        for (int nt = 0; nt < 8; nt++)
#pragma unroll
            for (int j = 0; j < 4; j++) D[mi][nt][j] = 0.f;

    const int lrow = tid >> 2, lcol = (tid & 3) * 8;

    for (int k0 = 0; k0 < ND; k0 += 32) {
#pragma unroll
        for (int p = 0; p < 2; p++) {
            const int row = lrow + 64 * p;
            // X: fp32 -> split into hi/lo bf16 on the fly
            const float* xr = &X[(size_t)(m0 + row) * ND + k0 + lcol];
            float4 a = *(const float4*)&xr[0];
            float4 bq = *(const float4*)&xr[4];
            uint4 hh, ll;
            hh.x = packbf(a.x, a.y);
            hh.y = packbf(a.z, a.w);
            hh.z = packbf(bq.x, bq.y);
            hh.w = packbf(bq.z, bq.w);
            ll.x = packbf(a.x - bfround(a.x), a.y - bfround(a.y));
            ll.y = packbf(a.z - bfround(a.z), a.w - bfround(a.w));
            ll.z = packbf(bq.x - bfround(bq.x), bq.y - bfround(bq.y));
            ll.w = packbf(bq.z - bfround(bq.z), bq.w - bfround(bq.w));
            *(uint4*)&Xsh[row * 40 + lcol] = hh;
            *(uint4*)&Xsl[row * 40 + lcol] = ll;
            // W: pre-split bf16
            *(uint4*)&Wsh[row * 40 + lcol] = *(const uint4*)&Wh[(size_t)(n0 + row) * ND + k0 + lcol];
            *(uint4*)&Wsl[row * 40 + lcol] = *(const uint4*)&Wl[(size_t)(n0 + row) * ND + k0 + lcol];
        }
        __syncthreads();

        const u32* XH = (const u32*)Xsh;
        const u32* XL = (const u32*)Xsl;
        const u32* WH = (const u32*)Wsh;
        const u32* WL = (const u32*)Wsl;
#pragma unroll
        for (int c = 0; c < 2; c++) {
            u32 aH[2][4], aL[2][4];
#pragma unroll
            for (int mi = 0; mi < 2; mi++) {
                const int r0 = (mw + 16 * mi + g) * 20 + 8 * c + t;
                const int r1 = (mw + 16 * mi + g + 8) * 20 + 8 * c + t;
                aH[mi][0] = XH[r0]; aH[mi][1] = XH[r1];
                aH[mi][2] = XH[r0 + 4]; aH[mi][3] = XH[r1 + 4];
                aL[mi][0] = XL[r0]; aL[mi][1] = XL[r1];
                aL[mi][2] = XL[r0 + 4]; aL[mi][3] = XL[r1 + 4];
            }
#pragma unroll
            for (int nt = 0; nt < 8; nt++) {
                const int nb = (nw + 8 * nt + g) * 20 + 8 * c + t;
                const u32 bh0 = WH[nb], bh1 = WH[nb + 4];
                const u32 bl0 = WL[nb], bl1 = WL[nb + 4];
#pragma unroll
                for (int mi = 0; mi < 2; mi++) {
                    mma_bf16(D[mi][nt], aH[mi], bh0, bh1);
                    mma_bf16(D[mi][nt], aH[mi], bl0, bl1);
                    mma_bf16(D[mi][nt], aL[mi], bh0, bh1);
                }
            }
        }
        __syncthreads();
    }

#pragma unroll
    for (int mi = 0; mi < 2; mi++) {
#pragma unroll
        for (int nt = 0; nt < 8; nt++) {
            const int n = n0 + nw + 8 * nt + 2 * t;
            const float bb0 = bias[n], bb1 = bias[n + 1];
            const int h = n >> 6, dk = n & 63;
#pragma unroll
            for (int rr = 0; rr < 2; rr++) {
                const int m = m0 + mw + 16 * mi + g + 8 * rr;
                const float v0 = D[mi][nt][2 * rr + 0] + bb0;
                const float v1 = D[mi][nt][2 * rr + 1] + bb1;
                const int b = m >> 11, s = m & (NS - 1);
                const size_t off = (((size_t)(b * NH + h)) * NS + s) * NDK + dk;
                *(u32*)&Yh[off] = packbf(v0, v1);
                *(u32*)&Yl[off] = packbf(v0 - bfround(v0), v1 - bfround(v1));
            }
        }
    }
}

// ---------------------------------------------------------------------------
// Output projection (R12/R16 plain-LDS version)
// ---------------------------------------------------------------------------
__global__ __launch_bounds__(256) void proj_out(const float* __restrict__ bias,
                                                float* __restrict__ out) {
    __shared__ __align__(16) bf16 Xsh[128 * 40], Xsl[128 * 40];
    __shared__ __align__(16) bf16 Wsh[128 * 40], Wsl[128 * 40];

    const bf16* Xh = g_Ch;
    const bf16* Xl = g_Cl;
    const bf16* Wh = g_Wh + (size_t)3 * ND * ND;
    const bf16* Wl = g_Wl + (size_t)3 * ND * ND;

    const int tid = threadIdx.x;
    const int w = tid >> 5, lane = tid & 31, g = lane >> 2, t = lane & 3;
    const int m0 = blockIdx.y * 128, n0 = blockIdx.x * 128;
    const int mw = (w >> 1) * 32, nw = (w & 1) * 64;

    float D[2][8][4];
#pragma unroll
    for (int mi = 0; mi < 2; mi++)
#pragma unroll
        for (int nt = 0; nt < 8; nt++)
#pragma unroll
            for (int j = 0; j < 4; j++) D[mi][nt][j] = 0.f;

    const int lrow = tid >> 2, lcol = (tid & 3) * 8;

    for (int k0 = 0; k0 < ND; k0 += 32) {
#pragma unroll
        for (int p = 0; p < 2; p++) {
            const int row = lrow + 64 * p;
            *(uint4*)&Xsh[row * 40 + lcol] = *(const uint4*)&Xh[(size_t)(m0 + row) * ND + k0 + lcol];
            *(uint4*)&Xsl[row * 40 + lcol] = *(const uint4*)&Xl[(size_t)(m0 + row) * ND + k0 + lcol];
            *(uint4*)&Wsh[row * 40 + lcol] = *(const uint4*)&Wh[(size_t)(n0 + row) * ND + k0 + lcol];
            *(uint4*)&Wsl[row * 40 + lcol] = *(const uint4*)&Wl[(size_t)(n0 + row) * ND + k0 + lcol];
        }
        __syncthreads();

        const u32* XH = (const u32*)Xsh;
        const u32* XL = (const u32*)Xsl;
        const u32* WH = (const u32*)Wsh;
        const u32* WL = (const u32*)Wsl;
#pragma unroll
        for (int c = 0; c < 2; c++) {
            u32 aH[2][4], aL[2][4];
#pragma unroll
            for (int mi = 0; mi < 2; mi++) {
                const int r0 = (mw + 16 * mi + g) * 20 + 8 * c + t;
                const int r1 = (mw + 16 * mi + g + 8) * 20 + 8 * c + t;
                aH[mi][0] = XH[r0]; aH[mi][1] = XH[r1];
                aH[mi][2] = XH[r0 + 4]; aH[mi][3] = XH[r1 + 4];
                aL[mi][0] = XL[r0]; aL[mi][1] = XL[r1];
                aL[mi][2] = XL[r0 + 4]; aL[mi][3] = XL[r1 + 4];
            }
#pragma unroll
            for (int nt = 0; nt < 8; nt++) {
                const int nb = (nw + 8 * nt + g) * 20 + 8 * c + t;
                const u32 bh0 = WH[nb], bh1 = WH[nb + 4];
                const u32 bl0 = WL[nb], bl1 = WL[nb + 4];
#pragma unroll
                for (int mi = 0; mi < 2; mi++) {
                    mma_bf16(D[mi][nt], aH[mi], bh0, bh1);
                    mma_bf16(D[mi][nt], aH[mi], bl0, bl1);
                    mma_bf16(D[mi][nt], aL[mi], bh0, bh1);
                }
            }
        }
        __syncthreads();
    }

#pragma unroll
    for (int mi = 0; mi < 2; mi++) {
#pragma unroll
        for (int nt = 0; nt < 8; nt++) {
            const int n = n0 + nw + 8 * nt + 2 * t;
            const float bb0 = bias[n], bb1 = bias[n + 1];
#pragma unroll
            for (int rr = 0; rr < 2; rr++) {
                const int m = m0 + mw + 16 * mi + g + 8 * rr;
                float2 v = make_float2(D[mi][nt][2 * rr + 0] + bb0,
                                       D[mi][nt][2 * rr + 1] + bb1);
                *(float2*)&out[(size_t)m * ND + n] = v;
            }
        }
    }
}

// ---------------------------------------------------------------------------
// attn.mean (R16 structure)
// ---------------------------------------------------------------------------
__global__ __launch_bounds__(256) void mean_ew(float* __restrict__ out) {
    const int b = blockIdx.z;
    const int q = blockIdx.y;
    const int k = threadIdx.x * 8;
    const int tile = k >> 6;

    const u32* Pbase = g_S + (((size_t)(b * NS + q) * NH) * NS + k >> 1);
    float acc[8];
#pragma unroll
    for (int j = 0; j < 8; j++) acc[j] = 0.f;

#pragma unroll
    for (int h = 0; h < NH; h++) {
        const size_t bh = (size_t)(b * NH + h);
        const float m = g_M[bh * NS + q];
        const float zi = g_Z[bh * NS + q];
        const float mt = g_Mt[(bh * NTILE + tile) * NS + q];
        const float corr = ex2f(mt - m) * zi;
        uint4 pv = *(const uint4*)&Pbase[(size_t)h * (NS >> 1)];
        float2 p0 = h2f2(pv.x), p1 = h2f2(pv.y), p2 = h2f2(pv.z), p3 = h2f2(pv.w);
        acc[0] += p0.x * corr; acc[1] += p0.y * corr;
        acc[2] += p1.x * corr; acc[3] += p1.y * corr;
        acc[4] += p2.x * corr; acc[5] += p2.y * corr;
        acc[6] += p3.x * corr; acc[7] += p3.y * corr;
    }
    float4 oA = make_float4(acc[0] * 0.125f, acc[1] * 0.125f, acc[2] * 0.125f, acc[3] * 0.125f);
    float4 oB = make_float4(acc[4] * 0.125f, acc[5] * 0.125f, acc[6] * 0.125f, acc[7] * 0.125f);
    float* orow = &out[((size_t)(b * NS + q)) * NS + k];
    *(float4*)&orow[0] = oA;
    *(float4*)&orow[4] = oB;
}

// ---------------------------------------------------------------------------
// Flash attention (R16 champion: 128q x 64k, 2 CTAs/SM, ldmatrix + cp.async)
// ---------------------------------------------------------------------------
__global__ __launch_bounds__(256, 2) void flash_mma() {
    __shared__ __align__(16) bf16 Khs[64 * 72], Kls[64 * 72];
    __shared__ __align__(16) bf16 Vhs[64 * 72], Vls[64 * 72];
    __shared__ float madds[64];

    const int tid = threadIdx.x;
    const int w = tid >> 5, lane = tid & 31, g = lane >> 2, t = lane & 3;
    const int bh = blockIdx.y;
    const int b = bh >> 3, h = bh & 7;
    const int q0 = blockIdx.x * 128;
    const int qw = q0 + 16 * w;

    const bf16* Qhp = g_Qh + (size_t)bh * NS * NDK;
    const bf16* Qlp = g_Ql + (size_t)bh * NS * NDK;
    const bf16* Khp = g_Kh + (size_t)bh * NS * NDK;
    const bf16* Klp = g_Kl + (size_t)bh * NS * NDK;
    const bf16* Vhp = g_Vh + (size_t)bh * NS * NDK;
    const bf16* Vlp = g_Vl + (size_t)bh * NS * NDK;

    u32* Srow0 = g_S + (((size_t)(b * NS + qw + g) * NH + h) * NS >> 1);
    u32* Srow1 = g_S + (((size_t)(b * NS + qw + g + 8) * NH + h) * NS >> 1);

    const u32 kb_h = smem_u32p(Khs), kb_l = smem_u32p(Kls);
    const u32 vb_h = smem_u32p(Vhs), vb_l = smem_u32p(Vls);
    const u32 aoffK = ((lane & 7) * 72 + 8 * (lane >> 3)) * 2;
    const u32 aoffV = (((lane & 7) + 8 * ((lane >> 3) & 1)) * 72 + 8 * (lane >> 4)) * 2;

    u32 qH[4][4], qL[4][4];
#pragma unroll
    for (int c = 0; c < 4; c++) {
        const size_t r0 = (size_t)(qw + g) * NDK + 16 * c + 2 * t;
        const size_t r1 = (size_t)(qw + g + 8) * NDK + 16 * c + 2 * t;
        qH[c][0] = *(const u32*)&Qhp[r0]; qH[c][1] = *(const u32*)&Qhp[r1];
        qH[c][2] = *(const u32*)&Qhp[r0 + 8]; qH[c][3] = *(const u32*)&Qhp[r1 + 8];
        qL[c][0] = *(const u32*)&Qlp[r0]; qL[c][1] = *(const u32*)&Qlp[r1];
        qL[c][2] = *(const u32*)&Qlp[r0 + 8]; qL[c][3] = *(const u32*)&Qlp[r1 + 8];
    }

    float O[8][4];
#pragma unroll
    for (int dt = 0; dt < 8; dt++)
#pragma unroll
        for (int j = 0; j < 4; j++) O[dt][j] = 0.f;
    float m0r = MINIT, m1r = MINIT, z0 = 0.f, z1 = 0.f;

    const int srow = tid >> 3, sseg = tid & 7;

    for (int kt = 0; kt < NS; kt += 64) {
#pragma unroll
        for (int p = 0; p < 2; p++) {
            const int row = srow + 32 * p;
            const size_t go = (size_t)(kt + row) * NDK + sseg * 8;
            const u32 so = (u32)(row * 72 + sseg * 8) * 2;
            cp16(kb_h + so, &Khp[go]);
            cp16(kb_l + so, &Klp[go]);
            cp16(vb_h + so, &Vhp[go]);
            cp16(vb_l + so, &Vlp[go]);
        }
        CP_COMMIT();
        if (tid < 64) madds[tid] = g_madd[b * NS + kt + tid];
        CP_WAIT0();
        __syncthreads();

        float S[8][4];
#pragma unroll
        for (int nt = 0; nt < 8; nt++)
#pragma unroll
            for (int j = 0; j < 4; j++) S[nt][j] = 0.f;
#pragma unroll
        for (int nt = 0; nt < 8; nt++) {
#pragma unroll
            for (int cc = 0; cc < 2; cc++) {
                const u32 off = aoffK + (u32)(8 * nt * 72 + 32 * cc) * 2;
                u32 fH[4], fL[4];
                ldsm_x4(fH, kb_h + off);
                ldsm_x4(fL, kb_l + off);
                mma_bf16(S[nt], qH[2 * cc],     fH[0], fH[1]);
                mma_bf16(S[nt], qH[2 * cc],     fL[0], fL[1]);
                mma_bf16(S[nt], qL[2 * cc],     fH[0], fH[1]);
                mma_bf16(S[nt], qH[2 * cc + 1], fH[2], fH[3]);
                mma_bf16(S[nt], qH[2 * cc + 1], fL[2], fL[3]);
                mma_bf16(S[nt], qL[2 * cc + 1], fH[2], fH[3]);
            }
        }

        float rm0 = MINIT, rm1 = MINIT;
#pragma unroll
        for (int nt = 0; nt < 8; nt++) {
            const float ma = madds[8 * nt + 2 * t], mb = madds[8 * nt + 2 * t + 1];
            S[nt][0] = S[nt][0] * SCL2 + ma; S[nt][1] = S[nt][1] * SCL2 + mb;
            S[nt][2] = S[nt][2] * SCL2 + ma; S[nt][3] = S[nt][3] * SCL2 + mb;
            rm0 = fmaxf(rm0, fmaxf(S[nt][0], S[nt][1]));
            rm1 = fmaxf(rm1, fmaxf(S[nt][2], S[nt][3]));
        }
        rm0 = fmaxf(rm0, __shfl_xor_sync(0xffffffffu, rm0, 1));
        rm0 = fmaxf(rm0, __shfl_xor_sync(0xffffffffu, rm0, 2));
        rm1 = fmaxf(rm1, __shfl_xor_sync(0xffffffffu, rm1, 1));
        rm1 = fmaxf(rm1, __shfl_xor_sync(0xffffffffu, rm1, 2));
        const float mn0 = fmaxf(m0r, rm0), mn1 = fmaxf(m1r, rm1);
        const float al0 = ex2f(m0r - mn0);
        const float al1 = ex2f(m1r - mn1);
        if (t == 0) {
            const size_t mtb = ((size_t)bh * NTILE + (kt >> 6)) * NS;
            g_Mt[mtb + qw + g] = mn0;
            g_Mt[mtb + qw + g + 8] = mn1;
        }
        float rs0 = 0.f, rs1 = 0.f;
#pragma unroll
        for (int nt = 0; nt < 8; nt++) {
            const float p0 = ex2f(S[nt][0] - mn0);
            const float p1 = ex2f(S[nt][1] - mn0);
            const float p2 = ex2f(S[nt][2] - mn1);
            const float p3 = ex2f(S[nt][3] - mn1);
            S[nt][0] = p0; S[nt][1] = p1; S[nt][2] = p2; S[nt][3] = p3;
            const int col2 = (kt + 8 * nt + 2 * t) >> 1;
            Srow0[col2] = packhf(p0, p1);
            Srow1[col2] = packhf(p2, p3);
            rs0 += p0 + p1; rs1 += p2 + p3;
        }
        rs0 += __shfl_xor_sync(0xffffffffu, rs0, 1);
        rs0 += __shfl_xor_sync(0xffffffffu, rs0, 2);
        rs1 += __shfl_xor_sync(0xffffffffu, rs1, 1);
        rs1 += __shfl_xor_sync(0xffffffffu, rs1, 2);
        z0 = z0 * al0 + rs0; z1 = z1 * al1 + rs1;
        m0r = mn0; m1r = mn1;
#pragma unroll
        for (int dt = 0; dt < 8; dt++) {
            O[dt][0] *= al0; O[dt][1] *= al0;
            O[dt][2] *= al1; O[dt][3] *= al1;
        }

        u32 pH[4][4], pL[4][4];
#pragma unroll
        for (int c = 0; c < 4; c++) {
            const float a0 = S[2 * c][0],     a1 = S[2 * c][1];
            const float a2 = S[2 * c][2],     a3 = S[2 * c][3];
            const float b0 = S[2 * c + 1][0], b1 = S[2 * c + 1][1];
            const float b2 = S[2 * c + 1][2], b3 = S[2 * c + 1][3];
            pH[c][0] = packbf(a0, a1); pH[c][1] = packbf(a2, a3);
            pH[c][2] = packbf(b0, b1); pH[c][3] = packbf(b2, b3);
            pL[c][0] = packbf(a0 - bfround(a0), a1 - bfround(a1));
            pL[c][1] = packbf(a2 - bfround(a2), a3 - bfround(a3));
            pL[c][2] = packbf(b0 - bfround(b0), b1 - bfround(b1));
            pL[c][3] = packbf(b2 - bfround(b2), b3 - bfround(b3));
        }

#pragma unroll
        for (int c = 0; c < 4; c++) {
#pragma unroll
            for (int dd = 0; dd < 4; dd++) {
                const u32 off = aoffV + (u32)(16 * c * 72 + 16 * dd) * 2;
                u32 vH[4], vL[4];
                ldsm_x4_t(vH, vb_h + off);
                ldsm_x4_t(vL, vb_l + off);
                mma_bf16(O[2 * dd],     pH[c], vH[0], vH[1]);
                mma_bf16(O[2 * dd],     pH[c], vL[0], vL[1]);
                mma_bf16(O[2 * dd],     pL[c], vH[0], vH[1]);
                mma_bf16(O[2 * dd + 1], pH[c], vH[2], vH[3]);
                mma_bf16(O[2 * dd + 1], pH[c], vL[2], vL[3]);
                mma_bf16(O[2 * dd + 1], pL[c], vH[2], vH[3]);
            }
        }
        __syncthreads();
    }

    const float inv0 = (z0 > 0.f) ? 1.f / z0 : 0.f;
    const float inv1 = (z1 > 0.f) ? 1.f / z1 : 0.f;
#pragma unroll
    for (int dt = 0; dt < 8; dt++) {
        const int d = 8 * dt + 2 * t;
        const float v0 = O[dt][0] * inv0, v1 = O[dt][1] * inv0;
        const float v2 = O[dt][2] * inv1, v3 = O[dt][3] * inv1;
        const size_t o0 = ((size_t)(b * NS + qw + g)) * ND + h * NDK + d;
        const size_t o1 = ((size_t)(b * NS + qw + g + 8)) * ND + h * NDK + d;
        *(u32*)&g_Ch[o0] = packbf(v0, v1);
        *(u32*)&g_Cl[o0] = packbf(v0 - bfround(v0), v1 - bfround(v1));
        *(u32*)&g_Ch[o1] = packbf(v2, v3);
        *(u32*)&g_Cl[o1] = packbf(v2 - bfround(v2), v3 - bfround(v3));
    }
    if (t == 0) {
        g_M[(size_t)bh * NS + qw + g] = m0r;
        g_M[(size_t)bh * NS + qw + g + 8] = m1r;
        g_Z[(size_t)bh * NS + qw + g] = inv0;
        g_Z[(size_t)bh * NS + qw + g + 8] = inv1;
    }
}

// ---------------------------------------------------------------------------
extern "C" void kernel_launch(void* const* d_in, const int* in_sizes, int n_in,
                              void* d_out, int out_size) {
    const float* qkv[3] = {0, 0, 0};
    const float* Ws[4] = {0, 0, 0, 0};
    const float* bs[4] = {0, 0, 0, 0};
    const void* maskraw = 0;
    int nqkv = 0, nW = 0, nb = 0;
    for (int i = 0; i < n_in; i++) {
        const int sz = in_sizes[i];
        if (sz == NB * NS * ND) { if (nqkv < 3) qkv[nqkv++] = (const float*)d_in[i]; }
        else if (sz == ND * ND) { if (nW < 4) Ws[nW++] = (const float*)d_in[i]; }
        else if (sz == ND)      { if (nb < 4) bs[nb++] = (const float*)d_in[i]; }
        else if (sz == NB * NS) { maskraw = d_in[i]; }
    }
    float* out = (float*)d_out;

    mask_detect<<<1, 256>>>((const unsigned char*)maskraw);
    mask_convert<<<(NB * NS + 255) / 256, 256>>>(maskraw);

    const int nWel = ND * ND;
    split_w<<<dim3(nWel / 4 / 256, 1, 4), 256>>>(Ws[0], Ws[1], Ws[2], Ws[3]);

    proj_qkv<<<dim3(ND / 128, (NB * NS) / 128, 3), 256>>>(
        qkv[0], qkv[1], qkv[2], bs[0], bs[1], bs[2]);

    flash_mma<<<dim3(NS / 128, NB * NH), 256>>>();

    proj_out<<<dim3(ND / 128, (NB * NS) / 128), 256>>>(bs[3], out);

    const long long need = (long long)NB * NS * ND + (long long)NB * NS * NS;
    if ((long long)out_size >= need) {
        mean_ew<<<dim3(1, NS, NB), 256>>>(out + (size_t)NB * NS * ND);
    }
}